// round 2
// baseline (speedup 1.0000x reference)
#include <cuda_runtime.h>
#include <cuda_bf16.h>

// Problem constants
#define T_STEPS 512
#define BATCH   64
#define HID     512
#define GATES   1536   // 3*HID
#define NLAYERS 2

// Scratch (device globals; no allocation)
__device__ float g_gates[(size_t)T_STEPS * BATCH * GATES];   // 201 MB
__device__ float g_buf1[(size_t)T_STEPS * BATCH * HID];      // 67 MB  (layer-1 output)

// Software grid barrier state
__device__ unsigned g_bar_arrive = 0;
__device__ unsigned g_bar_gen = 0;

// ---------------------------------------------------------------------------
// Input-projection GEMM:  C[m,n] = sum_k A[m,k] * W[n,k] + bias[n]
// A: (M, K) row-major   W: (N, K) row-major   C: (M, N)
// Tiles: BM=64, BN=64, BK=16, 256 threads, 4x4 register tile per thread.
// ---------------------------------------------------------------------------
#define BM 64
#define BN 64
#define BK 16

__global__ __launch_bounds__(256) void gemm_xw(
    const float* __restrict__ A, const float* __restrict__ W,
    const float* __restrict__ bias, float* __restrict__ C,
    int M, int N, int K)
{
    __shared__ float As[BK][BM];
    __shared__ float Ws[BK][BN];

    const int bm = blockIdx.y * BM;
    const int bn = blockIdx.x * BN;
    const int tid = threadIdx.x;
    const int tx = tid & 15;   // n direction
    const int ty = tid >> 4;   // m direction

    const int lr = tid >> 2;          // 0..63 (row within tile)
    const int lk = (tid & 3) * 4;     // 0,4,8,12 (k within tile)

    float acc[4][4];
#pragma unroll
    for (int i = 0; i < 4; i++)
#pragma unroll
        for (int j = 0; j < 4; j++) acc[i][j] = 0.0f;

    const float* Arow = A + (size_t)(bm + lr) * K + lk;
    const float* Wrow = W + (size_t)(bn + lr) * K + lk;

    for (int k0 = 0; k0 < K; k0 += BK) {
        float4 a4 = *(const float4*)(Arow + k0);
        float4 w4 = *(const float4*)(Wrow + k0);
        As[lk + 0][lr] = a4.x; As[lk + 1][lr] = a4.y;
        As[lk + 2][lr] = a4.z; As[lk + 3][lr] = a4.w;
        Ws[lk + 0][lr] = w4.x; Ws[lk + 1][lr] = w4.y;
        Ws[lk + 2][lr] = w4.z; Ws[lk + 3][lr] = w4.w;
        __syncthreads();

#pragma unroll
        for (int kk = 0; kk < BK; kk++) {
            float4 ra = *(const float4*)&As[kk][ty * 4];
            float4 rb = *(const float4*)&Ws[kk][tx * 4];
            float am[4] = {ra.x, ra.y, ra.z, ra.w};
            float bn_[4] = {rb.x, rb.y, rb.z, rb.w};
#pragma unroll
            for (int i = 0; i < 4; i++)
#pragma unroll
                for (int j = 0; j < 4; j++)
                    acc[i][j] += am[i] * bn_[j];
        }
        __syncthreads();
    }

#pragma unroll
    for (int i = 0; i < 4; i++) {
        int m = bm + ty * 4 + i;
        float* crow = C + (size_t)m * N + bn + tx * 4;
#pragma unroll
        for (int j = 0; j < 4; j++) {
            crow[j] = acc[i][j] + bias[bn + tx * 4 + j];
        }
    }
}

// ---------------------------------------------------------------------------
// Software grid barrier (all 128 CTAs resident: 1 CTA/SM due to 131KB SMEM).
// Release: every thread fences its writes, then one thread per CTA arrives.
// Acquire: waiter spins on generation counter, then fences before reuse.
// ---------------------------------------------------------------------------
__device__ __forceinline__ void grid_barrier(unsigned nblocks)
{
    __threadfence();          // publish this thread's h writes (release)
    __syncthreads();
    if (threadIdx.x == 0) {
        unsigned gen = *((volatile unsigned*)&g_bar_gen);
        unsigned prev = atomicAdd(&g_bar_arrive, 1u);
        if (prev == nblocks - 1) {
            g_bar_arrive = 0;
            __threadfence();
            atomicAdd(&g_bar_gen, 1u);
        } else {
            while (*((volatile unsigned*)&g_bar_gen) == gen) { }
        }
        __threadfence();      // acquire
    }
    __syncthreads();
}

// ---------------------------------------------------------------------------
// Persistent recurrent kernel: one launch runs all 512 time steps of a layer.
// grid = 128 CTAs = 32 j-tiles (16 hidden) x 4 b-tiles (16 batch), 256 thr.
// Each CTA caches its 48x512 W_hh slice in SMEM once; h_prev tile staged in
// SMEM each step (pitch 516 floats -> conflict-free float4 reads).
// ---------------------------------------------------------------------------
#define W_SMEM_FLOATS (48 * 512)           // 98304 B
#define H_PITCH 516                         // floats; 516 % 32 == 4 -> no conflicts
#define H_SMEM_FLOATS (16 * H_PITCH)        // 33024 B
#define SMEM_BYTES ((W_SMEM_FLOATS + H_SMEM_FLOATS) * 4)

__global__ __launch_bounds__(256) void gru_layer_persistent(
    const float* __restrict__ gx_all,  // (T, B, 3H) precomputed input gates
    const float* __restrict__ h0,      // (B, H)
    const float* __restrict__ Whh,     // (3H, H)
    const float* __restrict__ bhh,     // (3H)
    float* __restrict__ out)           // (T, B, H); out[t] doubles as h_t
{
    extern __shared__ float smem[];
    float* w_s = smem;                  // [48][512]  rows: gate*16 + jl
    float* h_s = smem + W_SMEM_FLOATS;  // [16][H_PITCH]

    const int jt = blockIdx.x & 31;
    const int bt = blockIdx.x >> 5;
    const int j0 = jt * 16;
    const int b0 = bt * 16;
    const int tid = threadIdx.x;

    // Load weight slice (48 rows x 512 floats), float4-coalesced
    for (int i = tid; i < 48 * 128; i += 256) {
        int row = i >> 7;          // 0..47
        int kq  = i & 127;
        int g = row >> 4;          // gate 0..2
        int r = row & 15;          // j within tile
        float4 v = *((const float4*)(Whh + (size_t)(g * HID + j0 + r) * HID) + kq);
        ((float4*)w_s)[row * 128 + kq] = v;
    }

    const int bl = tid & 15;       // batch within tile
    const int jl = tid >> 4;       // hidden within tile
    const int jg = j0 + jl;
    const int bg = b0 + bl;

    const float br_ = bhh[jg];
    const float bz_ = bhh[HID + jg];
    const float bn_ = bhh[2 * HID + jg];

    const float* wr = w_s + (0 * 16 + jl) * 512;
    const float* wz = w_s + (1 * 16 + jl) * 512;
    const float* wn = w_s + (2 * 16 + jl) * 512;
    const float* hp = h_s + bl * H_PITCH;

    const unsigned nblocks = gridDim.x;

    for (int t = 0; t < T_STEPS; t++) {
        const float* hprev = (t == 0) ? h0 : (out + (size_t)(t - 1) * BATCH * HID);

        // Stage h_prev tile: 16 rows x 128 float4, coalesced
        for (int i = tid; i < 16 * 128; i += 256) {
            int b  = i >> 7;
            int kq = i & 127;
            float4 v = *((const float4*)(hprev + (size_t)(b0 + b) * HID) + kq);
            *(float4*)&h_s[b * H_PITCH + kq * 4] = v;
        }
        __syncthreads();

        float ar = 0.f, az = 0.f, an = 0.f;
#pragma unroll 8
        for (int kq = 0; kq < 128; kq++) {
            float4 h4 = *(const float4*)(hp + 4 * kq);
            float4 r4 = *(const float4*)(wr + 4 * kq);
            float4 z4 = *(const float4*)(wz + 4 * kq);
            float4 n4 = *(const float4*)(wn + 4 * kq);
            ar += h4.x * r4.x + h4.y * r4.y + h4.z * r4.z + h4.w * r4.w;
            az += h4.x * z4.x + h4.y * z4.y + h4.z * z4.z + h4.w * z4.w;
            an += h4.x * n4.x + h4.y * n4.y + h4.z * n4.z + h4.w * n4.w;
        }

        const float* gxr = gx_all + (size_t)t * BATCH * GATES + (size_t)bg * GATES;
        float xr = gxr[jg];
        float xz = gxr[HID + jg];
        float xn = gxr[2 * HID + jg];

        float r = 1.0f / (1.0f + expf(-(xr + ar + br_)));
        float z = 1.0f / (1.0f + expf(-(xz + az + bz_)));
        float n = tanhf(xn + r * (an + bn_));

        float hpv = hp[jg];
        out[(size_t)t * BATCH * HID + (size_t)bg * HID + jg] = (1.0f - z) * n + z * hpv;

        grid_barrier(nblocks);   // includes release fence + trailing __syncthreads
    }
}

// ---------------------------------------------------------------------------
extern "C" void kernel_launch(void* const* d_in, const int* in_sizes, int n_in,
                              void* d_out, int out_size)
{
    const float* x    = (const float*)d_in[0];  // (T, B, I)
    const float* h0   = (const float*)d_in[1];  // (L, B, H)
    const float* w_ih = (const float*)d_in[2];  // (L, 3H, I)
    const float* w_hh = (const float*)d_in[3];  // (L, 3H, H)
    const float* b_ih = (const float*)d_in[4];  // (L, 3H)
    const float* b_hh = (const float*)d_in[5];  // (L, 3H)
    float* out_final  = (float*)d_out;          // (T, B, H)

    float* gates;
    float* buf1;
    cudaGetSymbolAddress((void**)&gates, g_gates);
    cudaGetSymbolAddress((void**)&buf1, g_buf1);

    static int smem_configured = 0;
    if (!smem_configured) {
        cudaFuncSetAttribute(gru_layer_persistent,
                             cudaFuncAttributeMaxDynamicSharedMemorySize, SMEM_BYTES);
        smem_configured = 1;
    }

    const int M = T_STEPS * BATCH;  // 32768
    const int K = HID;              // 512

    for (int l = 0; l < NLAYERS; l++) {
        const float* inp   = (l == 0) ? x : buf1;
        float*       out   = (l == NLAYERS - 1) ? out_final : buf1;
        const float* wih_l = w_ih + (size_t)l * GATES * HID;
        const float* whh_l = w_hh + (size_t)l * GATES * HID;
        const float* bih_l = b_ih + (size_t)l * GATES;
        const float* bhh_l = b_hh + (size_t)l * GATES;
        const float* h0_l  = h0 + (size_t)l * BATCH * HID;

        // gates_x = inp @ W_ih^T + b_ih   (all timesteps at once)
        dim3 ggrid(GATES / BN, M / BM);
        gemm_xw<<<ggrid, 256>>>(inp, wih_l, bih_l, gates, M, GATES, K);

        // full recurrence in ONE persistent launch (128 co-resident CTAs)
        gru_layer_persistent<<<128, 256, SMEM_BYTES>>>(gates, h0_l, whh_l, bhh_l, out);
    }
}

// round 3
// speedup vs baseline: 1.3407x; 1.3407x over previous
#include <cuda_runtime.h>
#include <cuda_bf16.h>
#include <cstdint>

// Problem constants
#define T_STEPS 512
#define BATCH   64
#define HID     512
#define GATES   1536   // 3*HID
#define NLAYERS 2

// Scratch (device globals; no allocation)
__device__ float g_gates[(size_t)T_STEPS * BATCH * GATES];   // 201 MB
__device__ float g_buf1[(size_t)T_STEPS * BATCH * HID];      // 67 MB  (layer-1 output)

// Per-batch-group software barriers (4 groups x 32 CTAs)
struct alignas(128) BarSt { unsigned arrive; unsigned gen; unsigned pad[30]; };
__device__ BarSt g_bars[4];

// ---------------------------------------------------------------------------
// TF32 tensor-core GEMM:  C[m,n] = sum_k A[m,k] * W[n,k] + bias[n]
// A: (M, K) row-major   W: (N, K) row-major   C: (M, N) row-major
// CTA tile 64(M) x 128(N), K staged 32 at a time. 256 threads = 8 warps in
// a 2(m) x 4(n) grid; warp tile 32x32 via 2x4 mma.m16n8k8 per k8 step.
// SMEM holds operands PRE-SCATTERED into fragment order so fragment loads
// are conflict-free LDS.128 (A) / LDS.64 (B).
// ---------------------------------------------------------------------------
#define GK 32   // K per stage

__device__ __forceinline__ uint32_t f32_to_tf32(float f) {
    uint32_t u;
    asm("cvt.rna.tf32.f32 %0, %1;" : "=r"(u) : "f"(f));
    return u;
}

__global__ __launch_bounds__(256) void gemm_tf32(
    const float* __restrict__ A, const float* __restrict__ W,
    const float* __restrict__ bias, float* __restrict__ C,
    int M, int N, int K)
{
    // [m_tile 0..3][k8 0..3][lane][reg]
    __shared__ uint32_t As[4][4][32][4];   // 8 KB
    __shared__ uint32_t Bs[16][4][32][2];  // 16 KB

    const int bm = blockIdx.y * 64;
    const int bn = blockIdx.x * 128;
    const int tid = threadIdx.x;
    const int wid = tid >> 5;
    const int lane = tid & 31;

    const int wm = wid & 1;        // warp m-half (32 rows)
    const int wn = wid >> 1;       // warp n-quarter (32 cols)
    const int mt0 = wm * 2;
    const int nt0 = wn * 4;

    float acc[2][4][4];
#pragma unroll
    for (int i = 0; i < 2; i++)
#pragma unroll
        for (int j = 0; j < 4; j++)
#pragma unroll
            for (int e = 0; e < 4; e++) acc[i][j][e] = 0.0f;

    for (int k0 = 0; k0 < K; k0 += GK) {
        // ---- stage A (64 x 32): 512 float4, 2 per thread, scatter to frag order
#pragma unroll
        for (int it = 0; it < 2; it++) {
            int idx4 = tid + it * 256;
            int m  = idx4 >> 3;          // 0..63
            int k  = (idx4 & 7) * 4;     // 0..28
            float4 v = *(const float4*)(A + (size_t)(bm + m) * K + k0 + k);
            int r = m & 15, mt = m >> 4;
            float vv[4] = {v.x, v.y, v.z, v.w};
#pragma unroll
            for (int e = 0; e < 4; e++) {
                int kf = k + e;
                int k8 = kf >> 3, kk = kf & 7;
                int ln = (r & 7) * 4 + (kk & 3);
                int rg = (kk >> 2) * 2 + (r >> 3);
                As[mt][k8][ln][rg] = f32_to_tf32(vv[e]);
            }
        }
        // ---- stage B/W (128 x 32): 1024 float4, 4 per thread
#pragma unroll
        for (int it = 0; it < 4; it++) {
            int idx4 = tid + it * 256;
            int n  = idx4 >> 3;          // 0..127
            int k  = (idx4 & 7) * 4;
            float4 v = *(const float4*)(W + (size_t)(bn + n) * K + k0 + k);
            int nt = n >> 3, nr = n & 7;
            float vv[4] = {v.x, v.y, v.z, v.w};
#pragma unroll
            for (int e = 0; e < 4; e++) {
                int kf = k + e;
                int k8 = kf >> 3, kk = kf & 7;
                int ln = nr * 4 + (kk & 3);
                int rg = kk >> 2;
                Bs[nt][k8][ln][rg] = f32_to_tf32(vv[e]);
            }
        }
        __syncthreads();

        // ---- compute: 4 k8 steps
#pragma unroll
        for (int k8 = 0; k8 < 4; k8++) {
            uint32_t a[2][4];
#pragma unroll
            for (int i = 0; i < 2; i++) {
                uint4 av = *(const uint4*)As[mt0 + i][k8][lane];
                a[i][0] = av.x; a[i][1] = av.y; a[i][2] = av.z; a[i][3] = av.w;
            }
            uint32_t b[4][2];
#pragma unroll
            for (int j = 0; j < 4; j++) {
                uint2 bv = *(const uint2*)Bs[nt0 + j][k8][lane];
                b[j][0] = bv.x; b[j][1] = bv.y;
            }
#pragma unroll
            for (int i = 0; i < 2; i++)
#pragma unroll
                for (int j = 0; j < 4; j++) {
                    asm volatile(
                        "mma.sync.aligned.m16n8k8.row.col.f32.tf32.tf32.f32 "
                        "{%0,%1,%2,%3}, {%4,%5,%6,%7}, {%8,%9}, {%0,%1,%2,%3};\n"
                        : "+f"(acc[i][j][0]), "+f"(acc[i][j][1]),
                          "+f"(acc[i][j][2]), "+f"(acc[i][j][3])
                        : "r"(a[i][0]), "r"(a[i][1]), "r"(a[i][2]), "r"(a[i][3]),
                          "r"(b[j][0]), "r"(b[j][1]));
                }
        }
        __syncthreads();
    }

    // ---- epilogue: add bias, store float2 per fragment half
#pragma unroll
    for (int i = 0; i < 2; i++) {
        int mrow = bm + (mt0 + i) * 16 + (lane >> 2);
#pragma unroll
        for (int j = 0; j < 4; j++) {
            int ncol = bn + (nt0 + j) * 8 + (lane & 3) * 2;
            float b0 = bias[ncol], b1 = bias[ncol + 1];
            float2 v0 = make_float2(acc[i][j][0] + b0, acc[i][j][1] + b1);
            float2 v1 = make_float2(acc[i][j][2] + b0, acc[i][j][3] + b1);
            *(float2*)(C + (size_t)mrow * N + ncol) = v0;
            *(float2*)(C + (size_t)(mrow + 8) * N + ncol) = v1;
        }
    }
}

// ---------------------------------------------------------------------------
// Per-batch-group grid barrier: only the 32 CTAs sharing a b-tile sync.
// ---------------------------------------------------------------------------
__device__ __forceinline__ void group_barrier(int grp, unsigned nb)
{
    __threadfence();          // publish h writes (release)
    __syncthreads();
    if (threadIdx.x == 0) {
        volatile unsigned* genp = &g_bars[grp].gen;
        unsigned gen = *genp;
        unsigned prev = atomicAdd(&g_bars[grp].arrive, 1u);
        if (prev == nb - 1) {
            g_bars[grp].arrive = 0;
            __threadfence();
            atomicAdd(&g_bars[grp].gen, 1u);
        } else {
            while (*genp == gen) { }
        }
        __threadfence();      // acquire
    }
    __syncthreads();
}

// ---------------------------------------------------------------------------
// Persistent recurrent kernel: one launch runs all 512 time steps of a layer.
// grid = 128 CTAs = 32 j-tiles (16 hidden) x 4 b-tiles (16 batch), 256 thr.
// ---------------------------------------------------------------------------
#define W_SMEM_FLOATS (48 * 512)           // 98304 B
#define H_PITCH 516                        // floats; no-conflict float4 reads
#define H_SMEM_FLOATS (16 * H_PITCH)       // 33024 B
#define SMEM_BYTES ((W_SMEM_FLOATS + H_SMEM_FLOATS) * 4)

__global__ __launch_bounds__(256) void gru_layer_persistent(
    const float* __restrict__ gx_all,  // (T, B, 3H) precomputed input gates
    const float* __restrict__ h0,      // (B, H)
    const float* __restrict__ Whh,     // (3H, H)
    const float* __restrict__ bhh,     // (3H)
    float* __restrict__ out)           // (T, B, H); out[t] doubles as h_t
{
    extern __shared__ float smem[];
    float* w_s = smem;                  // [48][512]
    float* h_s = smem + W_SMEM_FLOATS;  // [16][H_PITCH]

    const int jt = blockIdx.x & 31;
    const int bt = blockIdx.x >> 5;
    const int j0 = jt * 16;
    const int b0 = bt * 16;
    const int tid = threadIdx.x;

    // Load weight slice (48 rows x 512 floats) once
    for (int i = tid; i < 48 * 128; i += 256) {
        int row = i >> 7;
        int kq  = i & 127;
        int g = row >> 4;
        int r = row & 15;
        float4 v = *((const float4*)(Whh + (size_t)(g * HID + j0 + r) * HID) + kq);
        ((float4*)w_s)[row * 128 + kq] = v;
    }

    const int bl = tid & 15;
    const int jl = tid >> 4;
    const int jg = j0 + jl;
    const int bg = b0 + bl;

    const float br_ = bhh[jg];
    const float bz_ = bhh[HID + jg];
    const float bn_ = bhh[2 * HID + jg];

    const float* wr = w_s + (0 * 16 + jl) * 512;
    const float* wz = w_s + (1 * 16 + jl) * 512;
    const float* wn = w_s + (2 * 16 + jl) * 512;
    const float* hp = h_s + bl * H_PITCH;

    for (int t = 0; t < T_STEPS; t++) {
        const float* hprev = (t == 0) ? h0 : (out + (size_t)(t - 1) * BATCH * HID);

        // Prefetch input-side gates early (independent of h)
        const float* gxr = gx_all + (size_t)t * BATCH * GATES + (size_t)bg * GATES;
        float xr = __ldg(gxr + jg);
        float xz = __ldg(gxr + HID + jg);
        float xn = __ldg(gxr + 2 * HID + jg);

        // Stage h_prev tile: 16 rows x 128 float4, coalesced
        for (int i = tid; i < 16 * 128; i += 256) {
            int b  = i >> 7;
            int kq = i & 127;
            float4 v = *((const float4*)(hprev + (size_t)(b0 + b) * HID) + kq);
            *(float4*)&h_s[b * H_PITCH + kq * 4] = v;
        }
        __syncthreads();

        float ar = 0.f, az = 0.f, an = 0.f;
#pragma unroll 8
        for (int kq = 0; kq < 128; kq++) {
            float4 h4 = *(const float4*)(hp + 4 * kq);
            float4 r4 = *(const float4*)(wr + 4 * kq);
            float4 z4 = *(const float4*)(wz + 4 * kq);
            float4 n4 = *(const float4*)(wn + 4 * kq);
            ar += h4.x * r4.x + h4.y * r4.y + h4.z * r4.z + h4.w * r4.w;
            az += h4.x * z4.x + h4.y * z4.y + h4.z * z4.z + h4.w * z4.w;
            an += h4.x * n4.x + h4.y * n4.y + h4.z * n4.z + h4.w * n4.w;
        }

        float r = 1.0f / (1.0f + __expf(-(xr + ar + br_)));
        float z = 1.0f / (1.0f + __expf(-(xz + az + bz_)));
        float n = tanhf(xn + r * (an + bn_));

        float hpv = hp[jg];
        out[(size_t)t * BATCH * HID + (size_t)bg * HID + jg] = (1.0f - z) * n + z * hpv;

        if (t != T_STEPS - 1)
            group_barrier(bt, 32);   // only CTAs sharing this b-tile must sync
    }
}

// ---------------------------------------------------------------------------
extern "C" void kernel_launch(void* const* d_in, const int* in_sizes, int n_in,
                              void* d_out, int out_size)
{
    const float* x    = (const float*)d_in[0];  // (T, B, I)
    const float* h0   = (const float*)d_in[1];  // (L, B, H)
    const float* w_ih = (const float*)d_in[2];  // (L, 3H, I)
    const float* w_hh = (const float*)d_in[3];  // (L, 3H, H)
    const float* b_ih = (const float*)d_in[4];  // (L, 3H)
    const float* b_hh = (const float*)d_in[5];  // (L, 3H)
    float* out_final  = (float*)d_out;          // (T, B, H)

    float* gates;
    float* buf1;
    cudaGetSymbolAddress((void**)&gates, g_gates);
    cudaGetSymbolAddress((void**)&buf1, g_buf1);

    static int smem_configured = 0;
    if (!smem_configured) {
        cudaFuncSetAttribute(gru_layer_persistent,
                             cudaFuncAttributeMaxDynamicSharedMemorySize, SMEM_BYTES);
        smem_configured = 1;
    }

    const int M = T_STEPS * BATCH;  // 32768
    const int K = HID;              // 512

    for (int l = 0; l < NLAYERS; l++) {
        const float* inp   = (l == 0) ? x : buf1;
        float*       out   = (l == NLAYERS - 1) ? out_final : buf1;
        const float* wih_l = w_ih + (size_t)l * GATES * HID;
        const float* whh_l = w_hh + (size_t)l * GATES * HID;
        const float* bih_l = b_ih + (size_t)l * GATES;
        const float* bhh_l = b_hh + (size_t)l * GATES;
        const float* h0_l  = h0 + (size_t)l * BATCH * HID;

        // gates_x = inp @ W_ih^T + b_ih  (tensor cores, tf32)
        dim3 ggrid(GATES / 128, M / 64);
        gemm_tf32<<<ggrid, 256>>>(inp, wih_l, bih_l, gates, M, GATES, K);

        // full recurrence in ONE persistent launch (128 co-resident CTAs)
        gru_layer_persistent<<<128, 256, SMEM_BYTES>>>(gates, h0_l, whh_l, bhh_l, out);
    }
}

// round 4
// speedup vs baseline: 2.5743x; 1.9201x over previous
#include <cuda_runtime.h>
#include <cuda_bf16.h>
#include <cstdint>

// Problem constants
#define T_STEPS 512
#define BATCH   64
#define HID     512
#define GATES   1536   // 3*HID
#define NLAYERS 2

// Scratch (device globals; no allocation)
__device__ float g_gates[(size_t)T_STEPS * BATCH * GATES];   // 201 MB
__device__ float g_buf1[(size_t)T_STEPS * BATCH * HID];      // 67 MB

// Per-batch-group software barriers (4 groups x 32 CTAs)
struct alignas(128) BarSt { unsigned arrive; unsigned gen; unsigned pad[30]; };
__device__ BarSt g_bars[4];

__device__ __forceinline__ uint32_t f32_to_tf32(float f) {
    uint32_t u;
    asm("cvt.rna.tf32.f32 %0, %1;" : "=r"(u) : "f"(f));
    return u;
}

#define MMA_TF32(acc, a0, a1, a2, a3, b0, b1)                                  \
    asm volatile(                                                              \
        "mma.sync.aligned.m16n8k8.row.col.f32.tf32.tf32.f32 "                  \
        "{%0,%1,%2,%3}, {%4,%5,%6,%7}, {%8,%9}, {%0,%1,%2,%3};\n"              \
        : "+f"((acc)[0]), "+f"((acc)[1]), "+f"((acc)[2]), "+f"((acc)[3])       \
        : "r"(a0), "r"(a1), "r"(a2), "r"(a3), "r"(b0), "r"(b1))

// ---------------------------------------------------------------------------
// TF32 tensor-core GEMM:  C[m,n] = sum_k A[m,k] * W[n,k] + bias[n]
// CTA tile 64(M) x 128(N); SMEM pre-scattered to fragment order.
// ---------------------------------------------------------------------------
#define GK 32

__global__ __launch_bounds__(256) void gemm_tf32(
    const float* __restrict__ A, const float* __restrict__ W,
    const float* __restrict__ bias, float* __restrict__ C,
    int M, int N, int K)
{
    __shared__ uint32_t As[4][4][32][4];
    __shared__ uint32_t Bs[16][4][32][2];

    const int bm = blockIdx.y * 64;
    const int bn = blockIdx.x * 128;
    const int tid = threadIdx.x;
    const int wid = tid >> 5;
    const int lane = tid & 31;

    const int wm = wid & 1;
    const int wn = wid >> 1;
    const int mt0 = wm * 2;
    const int nt0 = wn * 4;

    float acc[2][4][4];
#pragma unroll
    for (int i = 0; i < 2; i++)
#pragma unroll
        for (int j = 0; j < 4; j++)
#pragma unroll
            for (int e = 0; e < 4; e++) acc[i][j][e] = 0.0f;

    for (int k0 = 0; k0 < K; k0 += GK) {
#pragma unroll
        for (int it = 0; it < 2; it++) {
            int idx4 = tid + it * 256;
            int m  = idx4 >> 3;
            int k  = (idx4 & 7) * 4;
            float4 v = *(const float4*)(A + (size_t)(bm + m) * K + k0 + k);
            int r = m & 15, mt = m >> 4;
            float vv[4] = {v.x, v.y, v.z, v.w};
#pragma unroll
            for (int e = 0; e < 4; e++) {
                int kf = k + e;
                int k8 = kf >> 3, kk = kf & 7;
                int ln = (r & 7) * 4 + (kk & 3);
                int rg = (kk >> 2) * 2 + (r >> 3);
                As[mt][k8][ln][rg] = f32_to_tf32(vv[e]);
            }
        }
#pragma unroll
        for (int it = 0; it < 4; it++) {
            int idx4 = tid + it * 256;
            int n  = idx4 >> 3;
            int k  = (idx4 & 7) * 4;
            float4 v = *(const float4*)(W + (size_t)(bn + n) * K + k0 + k);
            int nt = n >> 3, nr = n & 7;
            float vv[4] = {v.x, v.y, v.z, v.w};
#pragma unroll
            for (int e = 0; e < 4; e++) {
                int kf = k + e;
                int k8 = kf >> 3, kk = kf & 7;
                int ln = nr * 4 + (kk & 3);
                int rg = kk >> 2;
                Bs[nt][k8][ln][rg] = f32_to_tf32(vv[e]);
            }
        }
        __syncthreads();

#pragma unroll
        for (int k8 = 0; k8 < 4; k8++) {
            uint32_t a[2][4];
#pragma unroll
            for (int i = 0; i < 2; i++) {
                uint4 av = *(const uint4*)As[mt0 + i][k8][lane];
                a[i][0] = av.x; a[i][1] = av.y; a[i][2] = av.z; a[i][3] = av.w;
            }
            uint32_t b[4][2];
#pragma unroll
            for (int j = 0; j < 4; j++) {
                uint2 bv = *(const uint2*)Bs[nt0 + j][k8][lane];
                b[j][0] = bv.x; b[j][1] = bv.y;
            }
#pragma unroll
            for (int i = 0; i < 2; i++)
#pragma unroll
                for (int j = 0; j < 4; j++)
                    MMA_TF32(acc[i][j], a[i][0], a[i][1], a[i][2], a[i][3],
                             b[j][0], b[j][1]);
        }
        __syncthreads();
    }

#pragma unroll
    for (int i = 0; i < 2; i++) {
        int mrow = bm + (mt0 + i) * 16 + (lane >> 2);
#pragma unroll
        for (int j = 0; j < 4; j++) {
            int ncol = bn + (nt0 + j) * 8 + (lane & 3) * 2;
            float b0 = bias[ncol], b1 = bias[ncol + 1];
            float2 v0 = make_float2(acc[i][j][0] + b0, acc[i][j][1] + b1);
            float2 v1 = make_float2(acc[i][j][2] + b0, acc[i][j][3] + b1);
            *(float2*)(C + (size_t)mrow * N + ncol) = v0;
            *(float2*)(C + (size_t)(mrow + 8) * N + ncol) = v1;
        }
    }
}

// ---------------------------------------------------------------------------
// Per-batch-group grid barrier (32 CTAs per group)
// ---------------------------------------------------------------------------
__device__ __forceinline__ void group_barrier(int grp, unsigned nb)
{
    __threadfence();
    __syncthreads();
    if (threadIdx.x == 0) {
        volatile unsigned* genp = &g_bars[grp].gen;
        unsigned gen = *genp;
        unsigned prev = atomicAdd(&g_bars[grp].arrive, 1u);
        if (prev == nb - 1) {
            g_bars[grp].arrive = 0;
            __threadfence();
            atomicAdd(&g_bars[grp].gen, 1u);
        } else {
            while (*genp == gen) { }
        }
        __threadfence();
    }
    __syncthreads();
}

// ---------------------------------------------------------------------------
// Persistent recurrent kernel with tensor-core recurrent GEMM.
// grid = 128 CTAs = 32 j-tiles (16 hidden) x 4 b-groups (16 batch), 256 thr.
// Each CTA: out tile 16 batch x 48 gate-cols; k=512 split 8-ways over warps.
// W_hh fragments register-resident for all 512 steps.
// ---------------------------------------------------------------------------
#define HS_PITCH 520                       // floats per staged h row
#define PS_PITCH 50                        // floats per partial row
#define REC_SMEM_FLOATS (16 * HS_PITCH + 8 * 16 * PS_PITCH)
#define REC_SMEM_BYTES (REC_SMEM_FLOATS * 4)

__global__ __launch_bounds__(256, 1) void gru_layer_mma(
    const float* __restrict__ gx_all,  // (T, B, 3H)
    const float* __restrict__ h0,      // (B, H)
    const float* __restrict__ Whh,     // (3H, H)
    const float* __restrict__ bhh,     // (3H)
    float* __restrict__ out)           // (T, B, H); out[t] doubles as h_t
{
    extern __shared__ float sm[];
    float* h_s = sm;                   // [16][HS_PITCH] staged h (exact fp32)
    float* Ps  = sm + 16 * HS_PITCH;   // [8][16][PS_PITCH] per-warp partials

    const int jt = blockIdx.x & 31;
    const int bt = blockIdx.x >> 5;
    const int j0 = jt * 16;
    const int b0 = bt * 16;
    const int tid = threadIdx.x;
    const int w = tid >> 5;
    const int lane = tid & 31;

    // ---- load W_hh fragments into registers (once). Warp w owns k-slice
    // k8 in [w*8, w*8+8). B-frag (m16n8k8.col): lane -> col=lane>>2, k=lane&3.
    uint32_t wb0[6][8], wb1[6][8];
    {
        const int colq = lane >> 2;
        const int kq = lane & 3;
#pragma unroll
        for (int tl = 0; tl < 6; tl++) {
            int g = tl >> 1;                       // gate 0..2
            int col = j0 + (tl & 1) * 8 + colq;    // gate column (j part)
            const float* wrow = Whh + (size_t)(g * HID + col) * HID;
#pragma unroll
            for (int kk = 0; kk < 8; kk++) {
                int k = (w * 8 + kk) * 8 + kq;
                wb0[tl][kk] = f32_to_tf32(wrow[k]);
                wb1[tl][kk] = f32_to_tf32(wrow[k + 4]);
            }
        }
    }

    // gating mapping: thread -> (batch gb, output gj)
    const int gb = tid >> 4;
    const int gj = tid & 15;
    const int bg_g = b0 + gb;
    const int jg_g = j0 + gj;
    const float br_ = bhh[jg_g];
    const float bz_ = bhh[HID + jg_g];
    const float bn_ = bhh[2 * HID + jg_g];

    const int frow = lane >> 2;   // A-frag row 0..7
    const int fk = lane & 3;      // A-frag k 0..3

    for (int t = 0; t < T_STEPS; t++) {
        const float* hprev = (t == 0) ? h0 : out + (size_t)(t - 1) * BATCH * HID;

        // prefetch input-side gates (independent of h)
        const float* gxp = gx_all + (size_t)t * BATCH * GATES + (size_t)bg_g * GATES;
        float xr = __ldg(gxp + jg_g);
        float xz = __ldg(gxp + HID + jg_g);
        float xn = __ldg(gxp + 2 * HID + jg_g);

        // ---- stage h tile (16 x 512 fp32), coalesced
#pragma unroll
        for (int q = 0; q < 8; q++) {
            int f = q * 256 + tid;
            int r = f >> 7;          // 0..15
            int c4 = f & 127;
            float4 v = *((const float4*)(hprev + (size_t)(b0 + r) * HID) + c4);
            *(float4*)&h_s[r * HS_PITCH + c4 * 4] = v;
        }
        __syncthreads();

        // ---- MMA over this warp's k-slice: 8 k8-steps x 6 n-tiles
        float acc[6][4];
#pragma unroll
        for (int tl = 0; tl < 6; tl++) {
            acc[tl][0] = 0.f; acc[tl][1] = 0.f; acc[tl][2] = 0.f; acc[tl][3] = 0.f;
        }
#pragma unroll
        for (int kk = 0; kk < 8; kk++) {
            int kbase = (w * 8 + kk) * 8;
            uint32_t a0 = f32_to_tf32(h_s[frow * HS_PITCH + kbase + fk]);
            uint32_t a1 = f32_to_tf32(h_s[(frow + 8) * HS_PITCH + kbase + fk]);
            uint32_t a2 = f32_to_tf32(h_s[frow * HS_PITCH + kbase + 4 + fk]);
            uint32_t a3 = f32_to_tf32(h_s[(frow + 8) * HS_PITCH + kbase + 4 + fk]);
#pragma unroll
            for (int tl = 0; tl < 6; tl++)
                MMA_TF32(acc[tl], a0, a1, a2, a3, wb0[tl][kk], wb1[tl][kk]);
        }
        // store partials: Ps[w][row][tl*8 + col]
        {
            int m = lane >> 2;
            int ncb = 2 * (lane & 3);
#pragma unroll
            for (int tl = 0; tl < 6; tl++) {
                *(float2*)&Ps[(w * 16 + m) * PS_PITCH + tl * 8 + ncb] =
                    make_float2(acc[tl][0], acc[tl][1]);
                *(float2*)&Ps[(w * 16 + m + 8) * PS_PITCH + tl * 8 + ncb] =
                    make_float2(acc[tl][2], acc[tl][3]);
            }
        }
        __syncthreads();

        // ---- reduce 8 partials + gating (one thread per (b, j))
        float hr = 0.f, hz = 0.f, hn = 0.f;
#pragma unroll
        for (int ww = 0; ww < 8; ww++) {
            const float* p = &Ps[(ww * 16 + gb) * PS_PITCH];
            hr += p[gj];
            hz += p[16 + gj];
            hn += p[32 + gj];
        }
        float r = 1.0f / (1.0f + __expf(-(xr + hr + br_)));
        float z = 1.0f / (1.0f + __expf(-(xz + hz + bz_)));
        float n = tanhf(xn + r * (hn + bn_));

        float hpv = h_s[gb * HS_PITCH + jg_g];   // exact fp32 h_prev
        out[(size_t)t * BATCH * HID + (size_t)bg_g * HID + jg_g] =
            (1.0f - z) * n + z * hpv;

        if (t != T_STEPS - 1)
            group_barrier(bt, 32);
    }
}

// ---------------------------------------------------------------------------
extern "C" void kernel_launch(void* const* d_in, const int* in_sizes, int n_in,
                              void* d_out, int out_size)
{
    const float* x    = (const float*)d_in[0];
    const float* h0   = (const float*)d_in[1];
    const float* w_ih = (const float*)d_in[2];
    const float* w_hh = (const float*)d_in[3];
    const float* b_ih = (const float*)d_in[4];
    const float* b_hh = (const float*)d_in[5];
    float* out_final  = (float*)d_out;

    float* gates;
    float* buf1;
    cudaGetSymbolAddress((void**)&gates, g_gates);
    cudaGetSymbolAddress((void**)&buf1, g_buf1);

    static int smem_configured = 0;
    if (!smem_configured) {
        cudaFuncSetAttribute(gru_layer_mma,
                             cudaFuncAttributeMaxDynamicSharedMemorySize, REC_SMEM_BYTES);
        smem_configured = 1;
    }

    const int M = T_STEPS * BATCH;
    const int K = HID;

    for (int l = 0; l < NLAYERS; l++) {
        const float* inp   = (l == 0) ? x : buf1;
        float*       out   = (l == NLAYERS - 1) ? out_final : buf1;
        const float* wih_l = w_ih + (size_t)l * GATES * HID;
        const float* whh_l = w_hh + (size_t)l * GATES * HID;
        const float* bih_l = b_ih + (size_t)l * GATES;
        const float* bhh_l = b_hh + (size_t)l * GATES;
        const float* h0_l  = h0 + (size_t)l * BATCH * HID;

        dim3 ggrid(GATES / 128, M / 64);
        gemm_tf32<<<ggrid, 256>>>(inp, wih_l, bih_l, gates, M, GATES, K);

        gru_layer_mma<<<128, 256, REC_SMEM_BYTES>>>(gates, h0_l, whh_l, bhh_l, out);
    }
}

// round 5
// speedup vs baseline: 3.3555x; 1.3034x over previous
#include <cuda_runtime.h>
#include <cuda_bf16.h>
#include <cstdint>

// Problem constants
#define T_STEPS 512
#define BATCH   64
#define HID     512
#define GATES   1536   // 3*HID
#define NLAYERS 2

// Scratch (device globals; no allocation)
__device__ float g_gates[(size_t)T_STEPS * BATCH * GATES];   // 201 MB
__device__ float g_buf1[(size_t)T_STEPS * BATCH * HID];      // 67 MB
__device__ float g_wfrag[(size_t)192 * 64 * 32 * 2];         // 3 MB frag-ordered W_ih

// Per-batch-group software barriers (4 groups x 32 CTAs)
struct alignas(128) BarSt { unsigned arrive; unsigned gen; unsigned pad[30]; };
__device__ BarSt g_bars[4];

__device__ __forceinline__ uint32_t f32_to_tf32(float f) {
    uint32_t u;
    asm("cvt.rna.tf32.f32 %0, %1;" : "=r"(u) : "f"(f));
    return u;
}

#define MMA_TF32(acc, a0, a1, a2, a3, b0, b1)                                  \
    asm volatile(                                                              \
        "mma.sync.aligned.m16n8k8.row.col.f32.tf32.tf32.f32 "                  \
        "{%0,%1,%2,%3}, {%4,%5,%6,%7}, {%8,%9}, {%0,%1,%2,%3};\n"              \
        : "+f"((acc)[0]), "+f"((acc)[1]), "+f"((acc)[2]), "+f"((acc)[3])       \
        : "r"(a0), "r"(a1), "r"(a2), "r"(a3), "r"(b0), "r"(b1))

__device__ __forceinline__ void cp_async16(uint32_t dst, const void* src) {
    asm volatile("cp.async.cg.shared.global [%0], [%1], 16;" :: "r"(dst), "l"(src));
}

__device__ __forceinline__ unsigned ld_acq_gpu(unsigned* p) {
    unsigned v;
    asm volatile("ld.acquire.gpu.global.u32 %0, [%1];" : "=r"(v) : "l"(p) : "memory");
    return v;
}
__device__ __forceinline__ unsigned atom_add_rel_gpu(unsigned* p) {
    unsigned old;
    asm volatile("atom.add.release.gpu.global.u32 %0, [%1], 1;"
                 : "=r"(old) : "l"(p) : "memory");
    return old;
}

// ---------------------------------------------------------------------------
// Pre-convert W (N=1536, K=512 row-major fp32) into MMA B-fragment order:
// F[((nt*64 + k8)*32 + lane)*2 + r] = tf32(W[nt*8 + lane/4, k8*8 + lane%4 + 4r])
// ---------------------------------------------------------------------------
__global__ __launch_bounds__(256) void conv_wfrag(
    const float* __restrict__ W, uint32_t* __restrict__ F)
{
    int idx = blockIdx.x * 256 + threadIdx.x;   // 0 .. 786431
    int r    = idx & 1;
    int lane = (idx >> 1) & 31;
    int k8   = (idx >> 6) & 63;
    int nt   = idx >> 12;
    int n = nt * 8 + (lane >> 2);
    int k = k8 * 8 + (lane & 3) + 4 * r;
    F[idx] = f32_to_tf32(W[(size_t)n * HID + k]);
}

// ---------------------------------------------------------------------------
// GEMM v2:  C[m,n] = sum_k A[m,k] * W[n,k] + bias[n]
// A (M,K) row-major via cp.async double buffer; W via frag-ordered global.
// CTA tile 64(M) x 128(N); 8 warps = 2(m) x 4(n); warp tile 32x32.
// ---------------------------------------------------------------------------
#define AP 36   // A smem pitch (floats): 36 % 32 = 4 -> conflict-free frag LDS

__global__ __launch_bounds__(256) void gemm_tf32_v2(
    const float* __restrict__ A, const uint32_t* __restrict__ Wf,
    const float* __restrict__ bias, float* __restrict__ C,
    int M, int N, int K)
{
    __shared__ float As[2][64][AP];

    const int bm  = blockIdx.y * 64;
    const int bnt = blockIdx.x * 16;     // base n-tile (128 cols / 8)
    const int tid = threadIdx.x;
    const int wid = tid >> 5;
    const int lane = tid & 31;
    const int wm = wid & 1;
    const int wn = wid >> 1;
    const int frow = lane >> 2;
    const int fk = lane & 3;

    float acc[2][4][4];
#pragma unroll
    for (int i = 0; i < 2; i++)
#pragma unroll
        for (int j = 0; j < 4; j++)
#pragma unroll
            for (int e = 0; e < 4; e++) acc[i][j][e] = 0.0f;

    const int lm = tid >> 3;            // 0..31 (row, +32 second half)
    const int lk = (tid & 7) * 4;       // 0..28

    // issue stage loads for k0 into buffer buf
    auto issue_stage = [&](int k0, int buf) {
#pragma unroll
        for (int it = 0; it < 2; it++) {
            int m = lm + it * 32;
            uint32_t dst = (uint32_t)__cvta_generic_to_shared(&As[buf][m][lk]);
            cp_async16(dst, A + (size_t)(bm + m) * K + k0 + lk);
        }
        asm volatile("cp.async.commit_group;");
    };

    issue_stage(0, 0);
    int buf = 0;

    for (int k0 = 0; k0 < K; k0 += 32) {
        asm volatile("cp.async.wait_group 0;");
        __syncthreads();
        if (k0 + 32 < K) issue_stage(k0 + 32, buf ^ 1);

#pragma unroll
        for (int k8 = 0; k8 < 4; k8++) {
            const int kb = k8 * 8;
            const int k8g = (k0 >> 3) + k8;
            uint32_t b0[4], b1[4];
#pragma unroll
            for (int j = 0; j < 4; j++) {
                size_t nt = (size_t)(bnt + wn * 4 + j);
                const uint2 v = __ldg((const uint2*)(Wf + ((nt * 64 + k8g) * 32 + lane) * 2));
                b0[j] = v.x; b1[j] = v.y;
            }
            uint32_t a[2][4];
#pragma unroll
            for (int i = 0; i < 2; i++) {
                int r0 = wm * 32 + i * 16 + frow;
                a[i][0] = f32_to_tf32(As[buf][r0][kb + fk]);
                a[i][1] = f32_to_tf32(As[buf][r0 + 8][kb + fk]);
                a[i][2] = f32_to_tf32(As[buf][r0][kb + 4 + fk]);
                a[i][3] = f32_to_tf32(As[buf][r0 + 8][kb + 4 + fk]);
            }
#pragma unroll
            for (int i = 0; i < 2; i++)
#pragma unroll
                for (int j = 0; j < 4; j++)
                    MMA_TF32(acc[i][j], a[i][0], a[i][1], a[i][2], a[i][3],
                             b0[j], b1[j]);
        }
        buf ^= 1;
    }

    // epilogue: bias + store
#pragma unroll
    for (int i = 0; i < 2; i++) {
        int mrow = bm + wm * 32 + i * 16 + frow;
#pragma unroll
        for (int j = 0; j < 4; j++) {
            int ncol = (bnt + wn * 4 + j) * 8 + fk * 2;
            float c0 = bias[ncol], c1 = bias[ncol + 1];
            *(float2*)(C + (size_t)mrow * N + ncol) =
                make_float2(acc[i][j][0] + c0, acc[i][j][1] + c1);
            *(float2*)(C + (size_t)(mrow + 8) * N + ncol) =
                make_float2(acc[i][j][2] + c0, acc[i][j][3] + c1);
        }
    }
}

// ---------------------------------------------------------------------------
// Per-batch-group grid barrier (32 CTAs per group), acquire/release atomics.
// No gpu-scope fence -> no per-step L1 invalidate on the critical path.
// ---------------------------------------------------------------------------
__device__ __forceinline__ void group_barrier(int grp, unsigned nb)
{
    __syncthreads();
    if (threadIdx.x == 0) {
        unsigned gen0 = *(volatile unsigned*)&g_bars[grp].gen;
        unsigned prev = atom_add_rel_gpu(&g_bars[grp].arrive);
        if (prev == nb - 1) {
            *(volatile unsigned*)&g_bars[grp].arrive = 0;
            atom_add_rel_gpu(&g_bars[grp].gen);
        } else {
            while (ld_acq_gpu(&g_bars[grp].gen) == gen0) { }
        }
    }
    __syncthreads();
}

// ---------------------------------------------------------------------------
// Persistent recurrent kernel with tensor-core recurrent GEMM.
// grid = 128 CTAs = 32 j-tiles (16 hidden) x 4 b-groups (16 batch), 256 thr.
// W_hh fragments register-resident for all 512 steps.
// ---------------------------------------------------------------------------
#define HS_PITCH 520
#define PS_PITCH 50
#define REC_SMEM_FLOATS (16 * HS_PITCH + 8 * 16 * PS_PITCH)
#define REC_SMEM_BYTES (REC_SMEM_FLOATS * 4)

__global__ __launch_bounds__(256, 1) void gru_layer_mma(
    const float* __restrict__ gx_all,  // (T, B, 3H)
    const float* __restrict__ h0,      // (B, H)
    const float* __restrict__ Whh,     // (3H, H)
    const float* __restrict__ bhh,     // (3H)
    float* __restrict__ out)           // (T, B, H); out[t] doubles as h_t
{
    extern __shared__ float sm[];
    float* h_s = sm;                   // [16][HS_PITCH]
    float* Ps  = sm + 16 * HS_PITCH;   // [8][16][PS_PITCH]

    const int jt = blockIdx.x & 31;
    const int bt = blockIdx.x >> 5;
    const int j0 = jt * 16;
    const int b0 = bt * 16;
    const int tid = threadIdx.x;
    const int w = tid >> 5;
    const int lane = tid & 31;

    // W_hh fragments into registers (once). Warp w owns k8 in [w*8, w*8+8).
    uint32_t wb0[6][8], wb1[6][8];
    {
        const int colq = lane >> 2;
        const int kq = lane & 3;
#pragma unroll
        for (int tl = 0; tl < 6; tl++) {
            int g = tl >> 1;
            int col = j0 + (tl & 1) * 8 + colq;
            const float* wrow = Whh + (size_t)(g * HID + col) * HID;
#pragma unroll
            for (int kk = 0; kk < 8; kk++) {
                int k = (w * 8 + kk) * 8 + kq;
                wb0[tl][kk] = f32_to_tf32(wrow[k]);
                wb1[tl][kk] = f32_to_tf32(wrow[k + 4]);
            }
        }
    }

    const int gb = tid >> 4;
    const int gj = tid & 15;
    const int bg_g = b0 + gb;
    const int jg_g = j0 + gj;
    const float br_ = bhh[jg_g];
    const float bz_ = bhh[HID + jg_g];
    const float bn_ = bhh[2 * HID + jg_g];

    const int frow = lane >> 2;
    const int fk = lane & 3;

    // prefetch t=0 input-side gates
    const float* gxp = gx_all + (size_t)bg_g * GATES;
    float xr = __ldg(gxp + jg_g);
    float xz = __ldg(gxp + HID + jg_g);
    float xn = __ldg(gxp + 2 * HID + jg_g);

    for (int t = 0; t < T_STEPS; t++) {
        const float* hprev = (t == 0) ? h0 : out + (size_t)(t - 1) * BATCH * HID;

        // stage h tile (16 x 512 fp32), coalesced
#pragma unroll
        for (int q = 0; q < 8; q++) {
            int f = q * 256 + tid;
            int rr = f >> 7;
            int c4 = f & 127;
            float4 v = *((const float4*)(hprev + (size_t)(b0 + rr) * HID) + c4);
            *(float4*)&h_s[rr * HS_PITCH + c4 * 4] = v;
        }
        __syncthreads();

        // MMA over this warp's k-slice: 8 k8-steps x 6 n-tiles
        float acc[6][4];
#pragma unroll
        for (int tl = 0; tl < 6; tl++) {
            acc[tl][0] = 0.f; acc[tl][1] = 0.f; acc[tl][2] = 0.f; acc[tl][3] = 0.f;
        }
#pragma unroll
        for (int kk = 0; kk < 8; kk++) {
            int kbase = (w * 8 + kk) * 8;
            uint32_t a0 = f32_to_tf32(h_s[frow * HS_PITCH + kbase + fk]);
            uint32_t a1 = f32_to_tf32(h_s[(frow + 8) * HS_PITCH + kbase + fk]);
            uint32_t a2 = f32_to_tf32(h_s[frow * HS_PITCH + kbase + 4 + fk]);
            uint32_t a3 = f32_to_tf32(h_s[(frow + 8) * HS_PITCH + kbase + 4 + fk]);
#pragma unroll
            for (int tl = 0; tl < 6; tl++)
                MMA_TF32(acc[tl], a0, a1, a2, a3, wb0[tl][kk], wb1[tl][kk]);
        }
        {
            int m = lane >> 2;
            int ncb = 2 * (lane & 3);
#pragma unroll
            for (int tl = 0; tl < 6; tl++) {
                *(float2*)&Ps[(w * 16 + m) * PS_PITCH + tl * 8 + ncb] =
                    make_float2(acc[tl][0], acc[tl][1]);
                *(float2*)&Ps[(w * 16 + m + 8) * PS_PITCH + tl * 8 + ncb] =
                    make_float2(acc[tl][2], acc[tl][3]);
            }
        }
        __syncthreads();

        // reduce 8 partials + gating
        float hr = 0.f, hz = 0.f, hn = 0.f;
#pragma unroll
        for (int ww = 0; ww < 8; ww++) {
            const float* p = &Ps[(ww * 16 + gb) * PS_PITCH];
            hr += p[gj];
            hz += p[16 + gj];
            hn += p[32 + gj];
        }
        float r = 1.0f / (1.0f + __expf(-(xr + hr + br_)));
        float z = 1.0f / (1.0f + __expf(-(xz + hz + bz_)));
        float n = tanhf(xn + r * (hn + bn_));

        float hpv = h_s[gb * HS_PITCH + jg_g];
        out[(size_t)t * BATCH * HID + (size_t)bg_g * HID + jg_g] =
            (1.0f - z) * n + z * hpv;

        // prefetch next step's input-side gates (hides L2 behind barrier wait)
        int tn = (t + 1 < T_STEPS) ? t + 1 : t;
        const float* gxn = gx_all + (size_t)tn * BATCH * GATES + (size_t)bg_g * GATES;
        xr = __ldg(gxn + jg_g);
        xz = __ldg(gxn + HID + jg_g);
        xn = __ldg(gxn + 2 * HID + jg_g);

        if (t != T_STEPS - 1)
            group_barrier(bt, 32);
    }
}

// ---------------------------------------------------------------------------
extern "C" void kernel_launch(void* const* d_in, const int* in_sizes, int n_in,
                              void* d_out, int out_size)
{
    const float* x    = (const float*)d_in[0];
    const float* h0   = (const float*)d_in[1];
    const float* w_ih = (const float*)d_in[2];
    const float* w_hh = (const float*)d_in[3];
    const float* b_ih = (const float*)d_in[4];
    const float* b_hh = (const float*)d_in[5];
    float* out_final  = (float*)d_out;

    float* gates; float* buf1; uint32_t* wfrag;
    cudaGetSymbolAddress((void**)&gates, g_gates);
    cudaGetSymbolAddress((void**)&buf1, g_buf1);
    cudaGetSymbolAddress((void**)&wfrag, g_wfrag);

    static int smem_configured = 0;
    if (!smem_configured) {
        cudaFuncSetAttribute(gru_layer_mma,
                             cudaFuncAttributeMaxDynamicSharedMemorySize, REC_SMEM_BYTES);
        smem_configured = 1;
    }

    const int M = T_STEPS * BATCH;
    const int K = HID;

    for (int l = 0; l < NLAYERS; l++) {
        const float* inp   = (l == 0) ? x : buf1;
        float*       out   = (l == NLAYERS - 1) ? out_final : buf1;
        const float* wih_l = w_ih + (size_t)l * GATES * HID;
        const float* whh_l = w_hh + (size_t)l * GATES * HID;
        const float* bih_l = b_ih + (size_t)l * GATES;
        const float* bhh_l = b_hh + (size_t)l * GATES;
        const float* h0_l  = h0 + (size_t)l * BATCH * HID;

        conv_wfrag<<<3072, 256>>>(wih_l, wfrag);

        dim3 ggrid(GATES / 128, M / 64);
        gemm_tf32_v2<<<ggrid, 256>>>(inp, wfrag, bih_l, gates, M, GATES, K);

        gru_layer_mma<<<128, 256, REC_SMEM_BYTES>>>(gates, h0_l, whh_l, bhh_l, out);
    }
}